// round 17
// baseline (speedup 1.0000x reference)
#include <cuda_runtime.h>
#include <cuda_fp16.h>
#include <mma.h>
#include <math.h>
#include <stdint.h>

using namespace nvcuda;

#define N_NODES   100000
#define DEG       16
#define IN_DIM    128
#define OUT_DIM   32
#define EPS       1e-8f

// scratch (device globals: no allocation allowed in kernel_launch)
__device__ __half2 g_zh[N_NODES * (OUT_DIM / 2)];   // z rows in fp16 (only copy)
__device__ float   g_inorm[N_NODES];                // 1 / max(||z_i||, EPS)

__device__ __forceinline__ float2 h2f(uint32_t u) {
    __half2 h = *reinterpret_cast<__half2*>(&u);
    return __half22float2(h);
}

// ---------------------------------------------------------------------------
// Kernel 1: z = h @ W^T via wmma FP16 (m16n16k16), fp32 accumulate, fused
// inverse row norms. 128-row tiles (782 CTAs), 256 threads = 8 warps,
// 43.5KB smem -> 5 CTAs/SM (40 warps/SM). W staged half as often as the
// 64-row variant; h loads use streaming hint (read once).
// Warp w: m-tiles (w&3)*32 and +16, n-tile (w>>2)*16; 8 k-steps.
// Smem: Ws [32][136]h @0 (8704B), hs [128][136]h @8704 (34816B),
//       zsm [128][36]f ALIASES hs. total 43520 B.
// ---------------------------------------------------------------------------
#define LDH2 136
#define LDZ  36
#define GEMM_SMEM_BYTES 43520

__global__ __launch_bounds__(256) void gemm_wmma_kernel(
    const float* __restrict__ h, const float* __restrict__ W, int N)
{
    extern __shared__ char smraw[];
    __half* Ws  = reinterpret_cast<__half*>(smraw);           // [32][136]
    __half* hs  = reinterpret_cast<__half*>(smraw + 8704);    // [128][136]
    float*  zsm = reinterpret_cast<float*>(smraw + 8704);     // [128][36] alias

    const int tid  = threadIdx.x;
    const int wid  = tid >> 5;
    const int m0   = (wid & 3) * 32;
    const int n0   = (wid >> 2) * 16;
    const int row0 = blockIdx.x * 128;
    const unsigned FULL = 0xffffffffu;

    // ---- stage W -> fp16 smem ----
    const float4* W4 = reinterpret_cast<const float4*>(W);
    #pragma unroll
    for (int i = 0; i < 4; i++) {
        int f  = tid + i * 256;
        int n  = f >> 5;
        int k4 = f & 31;
        float4 v = __ldg(&W4[n * 32 + k4]);
        __half2 hx[2] = { __floats2half2_rn(v.x, v.y),
                          __floats2half2_rn(v.z, v.w) };
        *reinterpret_cast<uint2*>(&Ws[n * LDH2 + k4 * 4]) =
            *reinterpret_cast<const uint2*>(hx);
    }

    // ---- load 128-row h tile -> fp16 smem (streaming) ----
    const float4* h4 = reinterpret_cast<const float4*>(h);
    #pragma unroll
    for (int i = 0; i < 16; i++) {
        int f    = tid + i * 256;          // float4 index 0..4095
        int r    = f >> 5;                 // 0..127
        int k4   = f & 31;                 // 0..31
        int grow = row0 + r;
        if (grow >= N) grow = N - 1;
        float4 v = __ldcs(&h4[grow * 32 + k4]);
        __half2 hx[2] = { __floats2half2_rn(v.x, v.y),
                          __floats2half2_rn(v.z, v.w) };
        *reinterpret_cast<uint2*>(&hs[r * LDH2 + k4 * 4]) =
            *reinterpret_cast<const uint2*>(hx);
    }
    __syncthreads();

    // ---- wmma: 2 m-tiles x 1 n-tile x 8 k-steps per warp ----
    wmma::fragment<wmma::accumulator, 16, 16, 16, float> c0, c1;
    wmma::fill_fragment(c0, 0.0f);
    wmma::fill_fragment(c1, 0.0f);
    wmma::fragment<wmma::matrix_a, 16, 16, 16, __half, wmma::row_major> a0, a1;
    wmma::fragment<wmma::matrix_b, 16, 16, 16, __half, wmma::col_major> b0;
    #pragma unroll
    for (int ks = 0; ks < 8; ks++) {
        wmma::load_matrix_sync(b0, &Ws[n0 * LDH2 + ks * 16], LDH2);
        wmma::load_matrix_sync(a0, &hs[m0 * LDH2 + ks * 16], LDH2);
        wmma::load_matrix_sync(a1, &hs[(m0 + 16) * LDH2 + ks * 16], LDH2);
        wmma::mma_sync(c0, a0, b0, c0);
        wmma::mma_sync(c1, a1, b0, c1);
    }
    __syncthreads();                       // hs reads done -> zsm may overwrite

    wmma::store_matrix_sync(&zsm[m0 * LDZ + n0], c0, LDZ, wmma::mem_row_major);
    wmma::store_matrix_sync(&zsm[(m0 + 16) * LDZ + n0], c1, LDZ, wmma::mem_row_major);
    __syncthreads();

    // ---- epilogue: fp16 z (coalesced 32B/thread) + inverse norms ----
    // thread t: row = t>>1 (0..127), half q2 = t&1 -> dims 16*q2..16*q2+15
    int row = tid >> 1;
    int q2  = tid & 1;
    float4 z4[4];
    #pragma unroll
    for (int i = 0; i < 4; i++)
        z4[i] = *reinterpret_cast<const float4*>(&zsm[row * LDZ + q2 * 16 + i * 4]);
    float ss = 0.f;
    #pragma unroll
    for (int i = 0; i < 4; i++)
        ss += z4[i].x * z4[i].x + z4[i].y * z4[i].y
            + z4[i].z * z4[i].z + z4[i].w * z4[i].w;
    ss += __shfl_xor_sync(FULL, ss, 1);
    int grow = row0 + row;
    if (grow < N) {
        __half2 hx[8];
        #pragma unroll
        for (int i = 0; i < 4; i++) {
            hx[2 * i]     = __floats2half2_rn(z4[i].x, z4[i].y);
            hx[2 * i + 1] = __floats2half2_rn(z4[i].z, z4[i].w);
        }
        uint4* dst = reinterpret_cast<uint4*>(&g_zh[grow * 16 + q2 * 8]);
        dst[0] = reinterpret_cast<const uint4*>(hx)[0];
        dst[1] = reinterpret_cast<const uint4*>(hx)[1];
        if (q2 == 0)
            g_inorm[grow] = 1.0f / fmaxf(sqrtf(ss), EPS);
    }
}

// ---------------------------------------------------------------------------
// Kernel 2: per-node cosine attention + softmax + weighted aggregation.
// (byte-identical to R16 — parity-split half-warp per node, HFMA2 partials)
// ---------------------------------------------------------------------------
__global__ __launch_bounds__(256) void edge_agg_kernel(
    const float* __restrict__ beta_p, const int* __restrict__ src,
    float* __restrict__ out, int N)
{
    __shared__ float alpha_sm[8][32];

    const int warp_id = (blockIdx.x * blockDim.x + threadIdx.x) >> 5;
    if (warp_id * 2 >= N) return;

    const int w    = threadIdx.x >> 5;
    const int lane = threadIdx.x & 31;
    const int half = lane >> 4;
    const int hl   = lane & 15;
    const int odd  = (hl >> 3) & 1;
    const int sub  = hl & 7;
    int node = warp_id * 2 + half;
    const bool valid = (node < N);
    if (!valid) node = N - 1;

    const unsigned FULL = 0xffffffffu;
    const float beta = __ldg(beta_p);
    const __half* zh = reinterpret_cast<const __half*>(g_zh);

    // own z chunk: dims 4*sub .. 4*sub+3 (kept packed for HFMA2)
    uint2 zraw = *reinterpret_cast<const uint2*>(zh + node * 32 + 4 * sub);
    __half2 zdh0 = *reinterpret_cast<__half2*>(&zraw.x);
    __half2 zdh1 = *reinterpret_cast<__half2*>(&zraw.y);
    const float inv_nd = g_inorm[node];

    // all 16 src indices (uniform int4 loads)
    const int4* sp = reinterpret_cast<const int4*>(src + node * DEG);
    int4 s0 = __ldg(sp + 0);
    int4 s1 = __ldg(sp + 1);
    int4 s2 = __ldg(sp + 2);
    int4 s3 = __ldg(sp + 3);
    int si[DEG] = { s0.x, s0.y, s0.z, s0.w,  s1.x, s1.y, s1.z, s1.w,
                    s2.x, s2.y, s2.z, s2.w,  s3.x, s3.y, s3.z, s3.w };

    // gather order: item k = edge 2*R3[k] + odd  (R3 = 3-bit bit-reverse)
    constexpr int R3[8] = {0,4,2,6,1,5,3,7};
    int se[8];
    #pragma unroll
    for (int k = 0; k < 8; k++) {
        int e = 2 * R3[k];
        se[k] = odd ? si[e + 1] : si[e];
    }

    // own-edge (2*sub+odd) norm scale
    const int sid_own = __ldg(src + node * DEG + 2 * sub + odd);
    const float cc = __ldg(&g_inorm[sid_own]) * inv_nd;

    // gather: 4 dims of one edge per lane per LDG.64
    uint2 v[8];
    #pragma unroll
    for (int k = 0; k < 8; k++)
        v[k] = *reinterpret_cast<const uint2*>(zh + se[k] * 32 + 4 * sub);

    // per-lane 4-dim partial dots in packed half2 (4 instr/edge)
    float p[8];
    #pragma unroll
    for (int k = 0; k < 8; k++) {
        __half2 vx = *reinterpret_cast<__half2*>(&v[k].x);
        __half2 vy = *reinterpret_cast<__half2*>(&v[k].y);
        __half2 t  = __hfma2(vx, zdh0, __hmul2(vy, zdh1));
        p[k] = __half2float(__hadd(__low2half(t), __high2half(t)));
    }

    // ---- 3-level pack-tree over 8-lane subgroups (14 shfl/warp) ----
    const bool c4 = (sub & 4) != 0;
    const bool c2 = (sub & 2) != 0;
    const bool c1 = (sub & 1) != 0;

    float s[4];
    #pragma unroll
    for (int i = 0; i < 4; i++) {
        float a = p[2 * i]     + __shfl_xor_sync(FULL, p[2 * i], 4);
        float b = p[2 * i + 1] + __shfl_xor_sync(FULL, p[2 * i + 1], 4);
        s[i] = c4 ? b : a;
    }
    float q[2];
    #pragma unroll
    for (int i = 0; i < 2; i++) {
        float a = s[2 * i]     + __shfl_xor_sync(FULL, s[2 * i], 2);
        float b = s[2 * i + 1] + __shfl_xor_sync(FULL, s[2 * i + 1], 2);
        q[i] = c2 ? b : a;
    }
    float ra = q[0] + __shfl_xor_sync(FULL, q[0], 1);
    float rb = q[1] + __shfl_xor_sync(FULL, q[1], 1);
    float dotv = c1 ? rb : ra;         // dot of edge 2*sub+odd

    // softmax weight: exp(beta*cos) (constant -beta cancels; bounded)
    float esc = __expf(beta * (dotv * cc));

    // slot hl = (odd<<3)|sub holds esc of edge 2*sub+odd
    alpha_sm[w][lane] = esc;
    __syncwarp(FULL);

    // read own parity block: slot s holds edge 2s+odd = alpha of v[R3[s]]
    const float4* ap = reinterpret_cast<const float4*>(&alpha_sm[w][lane & 24]);
    float4 A0 = ap[0];
    float4 A1 = ap[1];
    float d = (A0.x + A0.y) + (A0.z + A0.w) + (A1.x + A1.y) + (A1.z + A1.w);

    float o0 = 0.f, o1 = 0.f, o2 = 0.f, o3 = 0.f;
    #define ACC(af, vm) do {                                   \
        float2 va = h2f((vm).x);                               \
        float2 vb = h2f((vm).y);                               \
        o0 = fmaf((af), va.x, o0);  o1 = fmaf((af), va.y, o1); \
        o2 = fmaf((af), vb.x, o2);  o3 = fmaf((af), vb.y, o3); \
    } while (0)
    ACC(A0.x, v[0]);  ACC(A0.y, v[4]);  ACC(A0.z, v[2]);  ACC(A0.w, v[6]);
    ACC(A1.x, v[1]);  ACC(A1.y, v[5]);  ACC(A1.z, v[3]);  ACC(A1.w, v[7]);
    #undef ACC

    // combine parity halves (same sub, other odd)
    o0 += __shfl_xor_sync(FULL, o0, 8);
    o1 += __shfl_xor_sync(FULL, o1, 8);
    o2 += __shfl_xor_sync(FULL, o2, 8);
    o3 += __shfl_xor_sync(FULL, o3, 8);
    float denom = d + __shfl_xor_sync(FULL, d, 8);

    if (valid && odd == 0) {
        float invd = 1.0f / denom;
        *reinterpret_cast<float4*>(&out[node * OUT_DIM + 4 * sub]) =
            make_float4(o0 * invd, o1 * invd, o2 * invd, o3 * invd);
    }
}

extern "C" void kernel_launch(void* const* d_in, const int* in_sizes, int n_in,
                              void* d_out, int out_size)
{
    const float* h    = (const float*)d_in[0];   // [N, 128]
    const float* W    = (const float*)d_in[1];   // [32, 128]
    const float* beta = (const float*)d_in[2];   // [1]
    const int*   src  = (const int*)d_in[3];     // [E]
    float* out = (float*)d_out;

    int N = in_sizes[0] / IN_DIM;                // 100000
    int ntiles = (N + 127) / 128;                // 782

    cudaFuncSetAttribute(gemm_wmma_kernel,
                         cudaFuncAttributeMaxDynamicSharedMemorySize,
                         GEMM_SMEM_BYTES);
    gemm_wmma_kernel<<<ntiles, 256, GEMM_SMEM_BYTES>>>(h, W, N);

    int nwarps  = (N + 1) / 2;
    int nblocks = (nwarps + 7) / 8;              // 8 warps / block
    edge_agg_kernel<<<nblocks, 256>>>(beta, src, out, N);
}